// round 17
// baseline (speedup 1.0000x reference)
#include <cuda_runtime.h>

typedef unsigned long long ull;

#define THREADS 256
#define SCALE_F 0.125f
#define FULLM   0xffffffffu
#define PAD     66

// smem float offsets
#define QSM 0
#define KSM (64 * PAD)          // 4224
#define GSM (2 * 64 * PAD)      // 8448  (pe^T in prologue, gate tiles in loop)
#define LGT (3 * 64 * PAD)      // 12672
#define FLG (4 * 64 * PAD)      // 16896: 8 per-warp saturation flags (int)
#define SMEM_FLOATS (FLG + 8)
#define SMEM_BYTES  (SMEM_FLOATS * 4)   // 67616 B -> 3 CTAs/SM

__device__ __forceinline__ ull fma2(ull a, ull b, ull c) {
    ull d;
    asm("fma.rn.f32x2 %0, %1, %2, %3;" : "=l"(d) : "l"(a), "l"(b), "l"(c));
    return d;
}
__device__ __forceinline__ float hsum2(ull a) {
    unsigned lo, hi;
    asm("mov.b64 {%0, %1}, %2;" : "=r"(lo), "=r"(hi) : "l"(a));
    return __uint_as_float(lo) + __uint_as_float(hi);
}
__device__ __forceinline__ float sigm(float x) {
    return __fdividef(1.0f, 1.0f + __expf(-x));
}

// synchronous 64x64 row-major tile load into smem [64][PAD]
__device__ __forceinline__ void load64(const float* __restrict__ src, float* dst, int tid) {
    #pragma unroll
    for (int r = 0; r < 4; ++r) {
        int f   = tid + r * THREADS;
        int row = f >> 4;
        int dp  = (f & 15) * 4;
        float4 v = ((const float4*)src)[f];
        float* p = dst + row * PAD + dp;
        *(float2*)p       = make_float2(v.x, v.y);
        *(float2*)(p + 2) = make_float2(v.z, v.w);
    }
}

// 64x64x64 register-tiled GEMM (strided frag rows): dst[row][key] = qs[row]·ks[key]
template <bool GATE>
__device__ __forceinline__ void gemm64(const float* qs, const float* ks, float* dst,
                                       int lane, int w)
{
    const int rowb = (w >> 2) * 32 + (lane >> 2);    // + i*8, i=0..3
    const int key0 = (w & 3) * 16 + (lane & 3) * 4;
    ull acc[4][4];
    #pragma unroll
    for (int i = 0; i < 4; ++i)
        #pragma unroll
        for (int j = 0; j < 4; ++j) acc[i][j] = 0ull;

    #pragma unroll 8
    for (int d = 0; d < 64; d += 2) {
        ull qv[4], kv[4];
        #pragma unroll
        for (int i = 0; i < 4; ++i) qv[i] = *(const ull*)(qs + (rowb + i * 8) * PAD + d);
        #pragma unroll
        for (int j = 0; j < 4; ++j) kv[j] = *(const ull*)(ks + (key0 + j) * PAD + d);
        #pragma unroll
        for (int i = 0; i < 4; ++i)
            #pragma unroll
            for (int j = 0; j < 4; ++j)
                acc[i][j] = fma2(qv[i], kv[j], acc[i][j]);
    }
    #pragma unroll
    for (int i = 0; i < 4; ++i) {
        float v0 = hsum2(acc[i][0]), v1 = hsum2(acc[i][1]);
        float v2 = hsum2(acc[i][2]), v3 = hsum2(acc[i][3]);
        if (GATE) {
            v0 = sigm(v0 * SCALE_F); v1 = sigm(v1 * SCALE_F);
            v2 = sigm(v2 * SCALE_F); v3 = sigm(v3 * SCALE_F);
        }
        float* p = dst + (rowb + i * 8) * PAD + key0;
        *(float2*)p       = make_float2(v0, v1);
        *(float2*)(p + 2) = make_float2(v2, v3);
    }
}

__global__ void __launch_bounds__(THREADS, 3)
cope_kernel(const float* __restrict__ q, const float* __restrict__ kmat,
            const float* __restrict__ pe, const int* __restrict__ flagp,
            float* __restrict__ out)
{
    extern __shared__ float sm[];
    float* qsm = sm + QSM;
    float* ksm = sm + KSM;
    float* gsm = sm + GSM;       // pe^T in prologue, gate tiles in loop
    float* lgt = sm + LGT;
    int*   wsat = (int*)(sm + FLG);

    const int tid  = threadIdx.x;
    const int w    = tid >> 5;
    const int lane = tid & 31;
    const int rh4  = (w >> 2) * 4;           // my gemm half's flag base
    const int b    = blockIdx.x >> 4;
    const int rb   = blockIdx.x & 15;
    const int rowg0 = b * 1024 + rb * 64;
    const float* kb = kmat + b * 65536;
    const int flag = *flagp;

    // ---- prologue: pe^T -> gsm; base rows -> qsm
    for (int i = tid; i < 4096; i += THREADS) {       // pe[d][n] -> gsm[n][d]
        int d = i >> 6, n = i & 63;
        gsm[n * PAD + d] = pe[i];
    }
    load64((flag ? q : kmat) + rowg0 * 64, qsm, tid);
    if (tid < 8) wsat[tid] = 0;
    __syncthreads();

    gemm64<false>(qsm, gsm, lgt, lane, w);            // logits_int table
    __syncthreads();
    if (tid < 64) lgt[tid * PAD + 64] = 0.0f;         // guard: pos==63 -> w=0 exact
    if (!flag) load64(q + rowg0 * 64, qsm, tid);      // gates always use q
    load64(kb + 15 * 4096, ksm, tid);                 // k tile 15
    __syncthreads();                                  // ksm(t15), lgt, qsm visible

    // ---- tile loop: (gemm if half live) -> barrier -> LDG -> pair-scan -> STS -> vote
    float cl[8];
    #pragma unroll
    for (int rr = 0; rr < 8; ++rr) cl[rr] = 0.0f;

    int kend = 0;
    for (int T = 15; ; --T) {
        // skip gemm if my half's 32 rows are all saturated (flags from last vote)
        bool halfsat = (wsat[rh4] & wsat[rh4 + 1] & wsat[rh4 + 2] & wsat[rh4 + 3]) != 0;
        if (!halfsat) gemm64<true>(qsm, ksm, gsm, lane, w);
        __syncthreads();                              // gsm ready; ksm reads done

        // early LDG of next k tile into registers (latency hidden by the scan)
        float4 kr[4];
        if (T > 0) {
            const float4* src = (const float4*)(kb + (T - 1) * 4096);
            #pragma unroll
            for (int r = 0; r < 4; ++r) kr[r] = src[tid + r * THREADS];
        }

        // pair-scan: warp w owns rows w*8..w*8+7; lane owns keys {2*lane, 2*lane+1}
        bool wsatl = true;
        #pragma unroll
        for (int rr = 0; rr < 8; ++rr) wsatl = wsatl && (cl[rr] >= 63.0f);

        if (wsatl) {
            // all 8 rows saturated: constant stores, no gsm reads, no shuffles
            #pragma unroll
            for (int rr = 0; rr < 8; ++rr) {
                float v = lgt[(w * 8 + rr) * PAD + 63];
                __stcs((float2*)(out + (rowg0 + w * 8 + rr) * 1024 + T * 64) + lane,
                       make_float2(v, v));
            }
        } else {
            #pragma unroll
            for (int rr = 0; rr < 8; ++rr) {
                const int r = w * 8 + rr;
                float2 g2 = *(const float2*)(gsm + r * PAD + 2 * lane);
                float S = g2.x + g2.y;                 // pair sum
                #pragma unroll
                for (int off = 1; off < 32; off <<= 1) {
                    float u = __shfl_down_sync(FULLM, S, off);
                    if (lane + off < 32) S += u;       // suffix over pairs
                }
                const float* lr = lgt + r * PAD;
                float p0 = fminf(cl[rr] + S, 63.0f);          // key 2*lane
                float p1 = fminf(cl[rr] + S - g2.x, 63.0f);   // key 2*lane+1
                float f0 = floorf(p0), f1 = floorf(p1);
                int   i0 = (int)f0,    i1 = (int)f1;
                float w0 = p0 - f0,    w1 = p1 - f1;
                float o0 = lr[i0 + 1] * w0 + lr[i0] * (1.0f - w0);
                float o1 = lr[i1 + 1] * w1 + lr[i1] * (1.0f - w1);
                __stcs((float2*)(out + (rowg0 + r) * 1024 + T * 64) + lane,
                       make_float2(o0, o1));
                cl[rr] += __shfl_sync(FULLM, S, 0);    // tile total
            }
        }

        // stage next k tile into ksm (reads of old ksm finished at barrier above)
        if (T > 0) {
            #pragma unroll
            for (int r = 0; r < 4; ++r) {
                int f = tid + r * THREADS;
                float* p = ksm + (f >> 4) * PAD + (f & 15) * 4;
                *(float2*)p       = make_float2(kr[r].x, kr[r].y);
                *(float2*)(p + 2) = make_float2(kr[r].z, kr[r].w);
            }
        }

        bool sat = true;
        #pragma unroll
        for (int rr = 0; rr < 8; ++rr) sat = sat && (cl[rr] >= 63.0f);
        if (lane == 0) wsat[w] = sat ? 1 : 0;         // publish for next tile's gemm skip
        bool alldone = __syncthreads_and(sat);        // publishes ksm + flags; frees gsm
        if (alldone) { kend = T * 64; break; }
        if (T == 0)  break;
    }

    // ---- saturated bulk fill: keys [0, kend) = logits_int[row][63]
    if (kend > 0) {
        #pragma unroll
        for (int rr = 0; rr < 8; ++rr) {
            int r = w * 8 + rr;
            float v = lgt[r * PAD + 63];
            float4 vv = make_float4(v, v, v, v);
            float* dst = out + (rowg0 + r) * 1024;
            for (int c = 4 * lane; c < kend; c += 128)
                __stcs((float4*)(dst + c), vv);
        }
    }
}

extern "C" void kernel_launch(void* const* d_in, const int* in_sizes, int n_in,
                              void* d_out, int out_size) {
    const float* q    = (const float*)d_in[0];
    const float* k    = (const float*)d_in[1];
    // d_in[2] = v (unused in mode 0)
    const float* pe   = (const float*)d_in[3];
    // d_in[4] = w_k (unused)
    const int*   flag = (const int*)d_in[5];
    float* out = (float*)d_out;

    cudaFuncSetAttribute(cope_kernel, cudaFuncAttributeMaxDynamicSharedMemorySize, SMEM_BYTES);
    const int grid = 32 * 16;   // 512 CTAs: 32 batches x 16 row-blocks of 64
    cope_kernel<<<grid, THREADS, SMEM_BYTES>>>(q, k, pe, flag, out);
}